// round 15
// baseline (speedup 1.0000x reference)
#include <cuda_runtime.h>
#include <cuda_bf16.h>
#include <math.h>

// Problem constants
#define N_Q   32768
#define M_R   16384
#define KNN   8

// Spatial grid: 32^3 cells of size 3.0 covering [-48, 48]^3.
// Out-of-range points clamp into edge cells (clamping only moves a point's
// CELL inward; edge-clipped sides of a visited box are exhaustive, so the
// termination bound is infinite on those sides).
#define GD        32
#define CELLS     (GD * GD * GD)        // 32768
#define HCELL     3.0f
#define INV_HCELL (1.0f / 3.0f)
#define HWORLD    48.0f

#define FULLMASK  0xffffffffu
#define INF_F     __int_as_float(0x7f800000)
// EMPTY slot sentinel: key of (+inf, 0x7fffffff). All finite-d' keys are smaller.
#define EMPTY_KEY 0xff8000007fffffffull

// Scan geometry: 64 blocks of 512 elements per array (R, Q)
#define SCAN_BLKS   64
#define SCAN_ELEMS  512

// ---- device scratch (allocation-free rule) ----
__device__ int    g_cntR[CELLS], g_startR[CELLS], g_curR[CELLS];
__device__ int    g_cntQ[CELLS], g_startQ[CELLS], g_curQ[CELLS];
__device__ int    g_blk[2 * SCAN_BLKS];
__device__ float4 g_refS[M_R];    // sorted refs: (-2x, -2y, -2z, |r|^2)
__device__ int    g_refId[M_R];   // sorted pos -> ORIGINAL ref index
__device__ float4 g_qS[N_Q];      // sorted queries: (x, y, z, |q|^2)
__device__ int    g_qId[N_Q];     // sorted pos -> original query index
__device__ int    g_fb[N_Q];      // fallback query slots
__device__ unsigned long long g_fbSeedK[N_Q]; // pass-A 8th-best key (>= true d8 key)
__device__ int    g_fbCnt;

// ---------------------------------------------------------------------------
// Sortable u64 key: (sign-flipped float d') << 32 | origId.
// f1 < f2  <=>  enc(f1) < enc(f2) for all finite floats, so u64 order ==
// lexicographic (d', origId) — exactly the verified tuple semantics.
// ---------------------------------------------------------------------------
__device__ __forceinline__ unsigned long long makeKey(float d, int oid) {
    unsigned u = __float_as_uint(d);
    u = (u & 0x80000000u) ? ~u : (u | 0x80000000u);
    return ((unsigned long long)u << 32) | (unsigned)oid;
}
__device__ __forceinline__ float keyDist(unsigned long long k) {
    unsigned s = (unsigned)(k >> 32);
    unsigned u = (s & 0x80000000u) ? (s & 0x7fffffffu) : ~s;
    return __uint_as_float(u);
}
__device__ __forceinline__ int keyOid(unsigned long long k) {
    return (int)(unsigned)k;
}

__device__ __forceinline__ int clampi(int v, int lo, int hi) {
    return v < lo ? lo : (v > hi ? hi : v);
}

__device__ __forceinline__ void cellCoords(float x, float y, float z,
                                           int& cx, int& cy, int& cz) {
    cx = clampi((int)floorf((x + HWORLD) * INV_HCELL), 0, GD - 1);
    cy = clampi((int)floorf((y + HWORLD) * INV_HCELL), 0, GD - 1);
    cz = clampi((int)floorf((z + HWORLD) * INV_HCELL), 0, GD - 1);
}

__device__ __forceinline__ int flatCell(int cx, int cy, int cz) {
    return (cz * GD + cy) * GD + cx;
}

// Sorted-ascending 8-best insert; caller guarantees key < b[7].
__device__ __forceinline__ void insert8k(unsigned long long key,
                                         unsigned long long (&b)[KNN]) {
    b[7] = key;
#pragma unroll
    for (int k = 7; k > 0; --k) {
        unsigned long long a = b[k - 1];
        if (b[k] < a) { b[k - 1] = b[k]; b[k] = a; }
    }
}

// ---------------------------------------------------------------------------
__global__ void zero_kernel() {
    int i = blockIdx.x * blockDim.x + threadIdx.x;
    if (i == 0)              g_fbCnt = 0;
    if (i < CELLS)           g_cntR[i] = 0;
    else if (i < 2 * CELLS)  g_cntQ[i - CELLS] = 0;
}

__global__ void count_all(const float* __restrict__ ref,
                          const float* __restrict__ q) {
    int i = blockIdx.x * blockDim.x + threadIdx.x;
    if (i < M_R) {
        int cx, cy, cz;
        cellCoords(ref[3 * i], ref[3 * i + 1], ref[3 * i + 2], cx, cy, cz);
        atomicAdd(&g_cntR[flatCell(cx, cy, cz)], 1);
    } else if (i < M_R + N_Q) {
        int j = i - M_R;
        int cx, cy, cz;
        cellCoords(q[3 * j], q[3 * j + 1], q[3 * j + 2], cx, cy, cz);
        atomicAdd(&g_cntQ[flatCell(cx, cy, cz)], 1);
    }
}

// ---------------------------------------------------------------------------
// Coalesced 2-kernel exclusive scan over the two 32768-entry count arrays.
// Phase 1: block-local scans + block totals. Phase 2: each block reduces the
// preceding block totals itself (64 values — cheap) and finalizes start/cur.
// ---------------------------------------------------------------------------
__global__ __launch_bounds__(SCAN_ELEMS) void scan1_kernel() {
    const bool isQ = blockIdx.x >= SCAN_BLKS;
    const int  seg = isQ ? (blockIdx.x - SCAN_BLKS) : blockIdx.x;
    const int* cnt   = isQ ? g_cntQ   : g_cntR;
    int*       start = isQ ? g_startQ : g_startR;

    const int tid  = threadIdx.x;
    const int lane = tid & 31;
    const int wid  = tid >> 5;
    const int g    = seg * SCAN_ELEMS + tid;

    int v = cnt[g];
    int x = v;
#pragma unroll
    for (int o = 1; o < 32; o <<= 1) {
        int n = __shfl_up_sync(FULLMASK, x, o);
        if (lane >= o) x += n;
    }

    __shared__ int sw[16];
    if (lane == 31) sw[wid] = x;
    __syncthreads();
    if (wid == 0) {
        int y = (lane < 16) ? sw[lane] : 0;
#pragma unroll
        for (int o = 1; o < 16; o <<= 1) {
            int n = __shfl_up_sync(FULLMASK, y, o);
            if (lane >= o) y += n;
        }
        if (lane < 16) sw[lane] = y;
    }
    __syncthreads();

    int base = wid ? sw[wid - 1] : 0;
    int excl = base + x - v;
    start[g] = excl;
    if (tid == SCAN_ELEMS - 1) g_blk[blockIdx.x] = excl + v;
}

__global__ __launch_bounds__(SCAN_ELEMS) void scan2_kernel() {
    const bool isQ = blockIdx.x >= SCAN_BLKS;
    const int  seg = isQ ? (blockIdx.x - SCAN_BLKS) : blockIdx.x;
    int* start = isQ ? g_startQ : g_startR;
    int* cur   = isQ ? g_curQ   : g_curR;

    __shared__ int red[64];
    const int tid  = threadIdx.x;
    const int base = isQ ? SCAN_BLKS : 0;
    if (tid < 64) red[tid] = (tid < seg) ? g_blk[base + tid] : 0;
    __syncthreads();
    if (tid < 32) {
        int v = red[tid] + red[tid + 32];
#pragma unroll
        for (int o = 16; o; o >>= 1) v += __shfl_down_sync(FULLMASK, v, o);
        if (tid == 0) red[0] = v;
    }
    __syncthreads();

    int off = red[0];
    int g = seg * SCAN_ELEMS + tid;
    int v = start[g] + off;
    start[g] = v;
    cur[g]   = v;
}

// ---------------------------------------------------------------------------
__global__ void scatter_all(const float* __restrict__ ref,
                            const float* __restrict__ q) {
    int i = blockIdx.x * blockDim.x + threadIdx.x;
    if (i < M_R) {
        float x = ref[3 * i], y = ref[3 * i + 1], z = ref[3 * i + 2];
        int cx, cy, cz;
        cellCoords(x, y, z, cx, cy, cz);
        int p = atomicAdd(&g_curR[flatCell(cx, cy, cz)], 1);
        g_refS[p]  = make_float4(-2.0f * x, -2.0f * y, -2.0f * z,
                                 x * x + y * y + z * z);
        g_refId[p] = i;
    } else if (i < M_R + N_Q) {
        int j = i - M_R;
        float x = q[3 * j], y = q[3 * j + 1], z = q[3 * j + 2];
        int cx, cy, cz;
        cellCoords(x, y, z, cx, cy, cz);
        int p = atomicAdd(&g_curQ[flatCell(cx, cy, cz)], 1);
        g_qS[p]  = make_float4(x, y, z, x * x + y * y + z * z);
        g_qId[p] = j;
    }
}

// ---------------------------------------------------------------------------
// PASS A: thread-per-query over the fixed 3x3x3 cell neighborhood.
// x-adjacent cells are contiguous in the sorted ref array, so each (zz,yy)
// row of up to 3 cells is ONE contiguous range: 9 range loops.
// Selection by u64 key == (d', origId) lex — reference-exact semantics.
// Invalid queries go to the fallback list with their 8th-best key as SEED
// (a proven upper bound on the true 8th-best key).
// ---------------------------------------------------------------------------
__global__ __launch_bounds__(128) void knnA_kernel(const float* __restrict__ flow,
                                                   float* __restrict__ out) {
    const int t = blockIdx.x * 128 + threadIdx.x;
    const float4 qp = g_qS[t];
    const float qx = qp.x, qy = qp.y, qz = qp.z, q2 = qp.w;

    int cx, cy, cz;
    cellCoords(qx, qy, qz, cx, cy, cz);
    const int x0 = max(cx - 1, 0), x1 = min(cx + 1, GD - 1);
    const int y0 = max(cy - 1, 0), y1 = min(cy + 1, GD - 1);
    const int z0 = max(cz - 1, 0), z1 = min(cz + 1, GD - 1);

    unsigned long long b[KNN];
#pragma unroll
    for (int k = 0; k < KNN; ++k) b[k] = EMPTY_KEY;
    float lim = INF_F;   // = keyDist(b[7])

    for (int zz = z0; zz <= z1; ++zz) {
        for (int yy = y0; yy <= y1; ++yy) {
            int cLo = flatCell(x0, yy, zz);
            int cHi = flatCell(x1, yy, zz);
            int j   = g_startR[cLo];
            int end = g_startR[cHi] + g_cntR[cHi];
#pragma unroll 4
            for (; j < end; ++j) {
                float4 r = g_refS[j];
                float d = fmaf(r.x, qx, fmaf(r.y, qy, fmaf(r.z, qz, r.w)));
                if (d <= lim) {                      // hot path: 1 setp
                    unsigned long long key = makeKey(d, g_refId[j]);
                    if (key < b[7]) {
                        insert8k(key, b);
                        lim = keyDist(b[7]);
                    }
                }
            }
        }
    }

    // Exact distance from query to the visited 3x3x3 box boundary.
    float lox = (x0 == 0)      ? -1e30f : (x0 * HCELL - HWORLD);
    float hix = (x1 == GD - 1) ?  1e30f : ((x1 + 1) * HCELL - HWORLD);
    float loy = (y0 == 0)      ? -1e30f : (y0 * HCELL - HWORLD);
    float hiy = (y1 == GD - 1) ?  1e30f : ((y1 + 1) * HCELL - HWORLD);
    float loz = (z0 == 0)      ? -1e30f : (z0 * HCELL - HWORLD);
    float hiz = (z1 == GD - 1) ?  1e30f : ((z1 + 1) * HCELL - HWORLD);

    float m = fminf(qx - lox, hix - qx);
    m = fminf(m, fminf(qy - loy, hiy - qy));
    m = fminf(m, fminf(qz - loz, hiz - qz));

    float b7d  = keyDist(b[7]);              // +inf if list not full
    float d8sq = fmaxf(b7d + q2, 0.0f);
    // STRICT <: a point exactly at distance m could win the origId tie-break.
    bool valid = (b[7] < EMPTY_KEY) && (m > 0.0f) && (d8sq < m * m);

    if (!valid) {
        int p = atomicAdd(&g_fbCnt, 1);
        g_fb[p]      = t;
        g_fbSeedK[p] = b[7];     // EMPTY_KEY if <8 found -> open gate
        return;
    }

    // IDW: POWER=2 -> w = 1/(d^2 + eps); no sqrt.
    float wsum = 0.0f, ax = 0.0f, ay = 0.0f, az = 0.0f;
#pragma unroll
    for (int k = 0; k < KNN; ++k) {
        float d2 = fmaxf(keyDist(b[k]) + q2, 0.0f);
        float w  = 1.0f / (d2 + 1e-8f);
        int  id  = keyOid(b[k]);
        wsum += w;
        ax = fmaf(w, flow[3 * id + 0], ax);
        ay = fmaf(w, flow[3 * id + 1], ay);
        az = fmaf(w, flow[3 * id + 2], az);
    }
    float inv = 1.0f / wsum;
    int qo = g_qId[t];
    out[3 * qo + 0] = ax * inv;
    out[3 * qo + 1] = ay * inv;
    out[3 * qo + 2] = az * inv;
}

// ---------------------------------------------------------------------------
// PASS B: warp-per-query SEEDED SHELL WALK for fallback queries (grid-stride
// over the fallback list). Shell/ring control flow transplanted from the
// round-10 kernel (correctness-verified). The seed key gates inserts
// (candidate kept iff key <= seedKey, i.e. key < seedKey+1) — a superset of
// the true top-8 since every true member's key <= seed. Termination bound
// uses min(seedD, warp-min of lane b[7]) — both are upper bounds on the true
// 8th distance. L2 traffic per query: ~sphere(r8) cells instead of all refs.
// ---------------------------------------------------------------------------
#define BWPB     8
#define B_BLOCKS 256    // 2048 warps, grid-stride
__global__ __launch_bounds__(BWPB * 32) void knnB_kernel(const float* __restrict__ flow,
                                                         float* __restrict__ out) {
    const int warpG  = blockIdx.x * BWPB + (threadIdx.x >> 5);
    const int nWarps = gridDim.x * BWPB;
    const int lane   = threadIdx.x & 31;
    const int fbCnt  = g_fbCnt;

    for (int w = warpG; w < fbCnt; w += nWarps) {
        const int t = g_fb[w];
        const unsigned long long gateKey = g_fbSeedK[w] + 1ull;  // key<=seed
        const float seedD = keyDist(gateKey);   // same d' bits as seed; +inf if open

        const float4 qp = g_qS[t];
        const float qx = qp.x, qy = qp.y, qz = qp.z, q2 = qp.w;

        int cx, cy, cz;
        cellCoords(qx, qy, qz, cx, cy, cz);

        unsigned long long b[KNN];
#pragma unroll
        for (int k = 0; k < KNN; ++k) b[k] = EMPTY_KEY;
        unsigned long long topLim = gateKey < EMPTY_KEY ? gateKey : EMPTY_KEY;
        float lim = keyDist(topLim);

        for (int s = 0; s < GD; ++s) {
            int x0 = max(cx - s, 0), x1 = min(cx + s, GD - 1);
            int y0 = max(cy - s, 0), y1 = min(cy + s, GD - 1);
            int z0 = max(cz - s, 0), z1 = min(cz + s, GD - 1);

            for (int zz = z0; zz <= z1; ++zz) {
                int dz = abs(zz - cz);
                for (int yy = y0; yy <= y1; ++yy) {
                    int dyz = max(abs(yy - cy), dz);
                    for (int xx = x0; xx <= x1; ++xx) {
                        if (max(abs(xx - cx), dyz) != s) continue;  // ring only
                        int c   = flatCell(xx, yy, zz);
                        int beg = g_startR[c];   // uniform addr: broadcast
                        int cnt = g_cntR[c];
                        for (int j0 = 0; j0 < cnt; j0 += 32) {
                            int j = j0 + lane;
                            if (j < cnt) {
                                float4 r = g_refS[beg + j];
                                float d = fmaf(r.x, qx,
                                          fmaf(r.y, qy, fmaf(r.z, qz, r.w)));
                                if (d <= lim) {
                                    unsigned long long key =
                                        makeKey(d, g_refId[beg + j]);
                                    if (key < topLim) {
                                        insert8k(key, b);
                                        topLim = b[7] < gateKey ? b[7] : gateKey;
                                        lim = keyDist(topLim);
                                    }
                                }
                            }
                        }
                    }
                }
            }

            bool full = (x0 == 0) && (y0 == 0) && (z0 == 0) &&
                        (x1 == GD - 1) && (y1 == GD - 1) && (z1 == GD - 1);
            if (full) break;

            // Upper bound on the true 8th distance: seed AND warp-min of
            // per-lane 8th-best (union-of-subsets argument, round-10).
            float ub = keyDist(b[7]);
#pragma unroll
            for (int o = 16; o; o >>= 1)
                ub = fminf(ub, __shfl_xor_sync(FULLMASK, ub, o));
            ub = fminf(ub, seedD);

            float lox = (x0 == 0)      ? -1e30f : (x0 * HCELL - HWORLD);
            float hix = (x1 == GD - 1) ?  1e30f : ((x1 + 1) * HCELL - HWORLD);
            float loy = (y0 == 0)      ? -1e30f : (y0 * HCELL - HWORLD);
            float hiy = (y1 == GD - 1) ?  1e30f : ((y1 + 1) * HCELL - HWORLD);
            float loz = (z0 == 0)      ? -1e30f : (z0 * HCELL - HWORLD);
            float hiz = (z1 == GD - 1) ?  1e30f : ((z1 + 1) * HCELL - HWORLD);

            float m = fminf(qx - lox, hix - qx);
            m = fminf(m, fminf(qy - loy, hiy - qy));
            m = fminf(m, fminf(qz - loz, hiz - qz));

            // STRICT > : a point exactly at the bound could win the oid tie.
            if (ub < 1e30f && m > 0.0f) {
                float d8sq = fmaxf(ub + q2, 0.0f);
                if (m * m > d8sq) break;
            }
        }

        // Merge: 8 warp-min pops over u64 keys (key order == (d',oid) lex).
        // Keys are unique (each ref seen by exactly one lane), so exactly one
        // lane pops per round. Lane r keeps the r-th neighbor.
        unsigned long long sel = EMPTY_KEY;
#pragma unroll
        for (int r = 0; r < KNN; ++r) {
            unsigned long long k = b[0];
#pragma unroll
            for (int o = 16; o; o >>= 1) {
                unsigned long long ok = __shfl_xor_sync(FULLMASK, k, o);
                if (ok < k) k = ok;
            }
            if (lane == r) sel = k;
            if (b[0] == k) {
#pragma unroll
                for (int kk = 0; kk < KNN - 1; ++kk) b[kk] = b[kk + 1];
                b[KNN - 1] = EMPTY_KEY;
            }
        }

        float ww = 0.0f, fx = 0.0f, fy = 0.0f, fz = 0.0f;
        if (lane < KNN) {
            float d2 = fmaxf(keyDist(sel) + q2, 0.0f);
            ww = 1.0f / (d2 + 1e-8f);
            int id = keyOid(sel);
            fx = ww * flow[3 * id + 0];
            fy = ww * flow[3 * id + 1];
            fz = ww * flow[3 * id + 2];
        }
#pragma unroll
        for (int o = 16; o; o >>= 1) {
            ww += __shfl_xor_sync(FULLMASK, ww, o);
            fx += __shfl_xor_sync(FULLMASK, fx, o);
            fy += __shfl_xor_sync(FULLMASK, fy, o);
            fz += __shfl_xor_sync(FULLMASK, fz, o);
        }

        if (lane == 0) {
            float inv = 1.0f / ww;
            int qo = g_qId[t];
            out[3 * qo + 0] = fx * inv;
            out[3 * qo + 1] = fy * inv;
            out[3 * qo + 2] = fz * inv;
        }
    }
}

// ---------------------------------------------------------------------------
extern "C" void kernel_launch(void* const* d_in, const int* in_sizes, int n_in,
                              void* d_out, int out_size) {
    const float* q   = (const float*)d_in[0];  // query_points [N,3]
    const float* r   = (const float*)d_in[1];  // ref_points   [M,3]
    const float* f   = (const float*)d_in[2];  // ref_flow     [M,3]
    float*       out = (float*)d_out;          // [N,3]

    zero_kernel<<<(2 * CELLS + 255) / 256, 256>>>();
    count_all<<<(M_R + N_Q + 255) / 256, 256>>>(r, q);
    scan1_kernel<<<2 * SCAN_BLKS, SCAN_ELEMS>>>();
    scan2_kernel<<<2 * SCAN_BLKS, SCAN_ELEMS>>>();
    scatter_all<<<(M_R + N_Q + 255) / 256, 256>>>(r, q);
    knnA_kernel<<<N_Q / 128, 128>>>(f, out);
    knnB_kernel<<<B_BLOCKS, BWPB * 32>>>(f, out);
}